// round 15
// baseline (speedup 1.0000x reference)
#include <cuda_runtime.h>
#include <math.h>
#include <stdint.h>

// ---------------------------------------------------------------------------
// DeepseekV2MoE: T=1024, H=2048, I=1408, E=16, top4 of 16 (grouped), IS=2816.
// R13: mma.sync TF32 GEMM, 128x128x16 CTA tile, 4 warps x (64x64) warp tiles
// (128 acc regs/thread), 4-stage cp.async pipeline, cvt.rna at fragment load.
// Router exact fp32; silu/combine fp32; deterministic routing.
// ---------------------------------------------------------------------------

#define T_TOK 1024
#define HID   2048
#define IMID  1408
#define NEXP  16
#define ISH   2816
#define NGROUP 4
#define TOPK   4
#define ROUTED_SCALING 2.5f

#define BM 128
#define BN 128
#define BK 16
#define NSTAGE 4
#define PADA 20            // As row pitch (floats)
#define PADB 136           // Bs row pitch (floats)
#define AS_FLOATS (BM * PADA)            // 2560
#define BS_FLOATS (BK * PADB)            // 2176
#define A_TOTAL   (NSTAGE * AS_FLOATS)   // 10240
#define DSM_FLOATS (A_TOTAL + NSTAGE * BS_FLOATS)
#define DSM_BYTES (DSM_FLOATS * 4)       // 75776 B

// ---------------- scratch (device globals; allocation-free) ----------------
__device__ float g_gu  [(size_t)NEXP * T_TOK * (2 * IMID)];
__device__ float g_down[(size_t)NEXP * T_TOK * HID];
__device__ float g_sgu [(size_t)T_TOK * (2 * ISH)];
__device__ int   g_topk_ids[T_TOK * TOPK];
__device__ float g_topk_w  [T_TOK * TOPK];
__device__ int   g_tok [NEXP * T_TOK];
__device__ float g_wt  [NEXP * T_TOK];
__device__ int   g_counts[NEXP];
__device__ int   g_slot[T_TOK * TOPK];

// ---------------------------------------------------------------------------
// helpers
// ---------------------------------------------------------------------------
__device__ __forceinline__ uint32_t smem_u32(const void* p) {
    uint32_t a;
    asm("{ .reg .u64 t; cvta.to.shared.u64 t, %1; cvt.u32.u64 %0, t; }"
        : "=r"(a) : "l"(p));
    return a;
}

__device__ __forceinline__ uint32_t f2tf32(float x) {
    uint32_t r;
    asm("cvt.rna.tf32.f32 %0, %1;" : "=r"(r) : "f"(x));
    return r;
}

__device__ __forceinline__ void cp_async16(uint32_t dst, const void* src, uint32_t src_sz) {
    asm volatile("cp.async.cg.shared.global [%0], [%1], 16, %2;"
                 :: "r"(dst), "l"(src), "r"(src_sz) : "memory");
}

#define CP_COMMIT() asm volatile("cp.async.commit_group;" ::: "memory")
#define CP_WAIT(n)  asm volatile("cp.async.wait_group %0;" :: "n"(n) : "memory")

__device__ __forceinline__ void mma_tf32(float c[4], const uint32_t a[4], const uint32_t b[2]) {
    asm volatile(
        "mma.sync.aligned.m16n8k8.row.col.f32.tf32.tf32.f32 "
        "{%0,%1,%2,%3}, {%4,%5,%6,%7}, {%8,%9}, {%0,%1,%2,%3};\n"
        : "+f"(c[0]), "+f"(c[1]), "+f"(c[2]), "+f"(c[3])
        : "r"(a[0]), "r"(a[1]), "r"(a[2]), "r"(a[3]), "r"(b[0]), "r"(b[1]));
}

// ---------------------------------------------------------------------------
// K1: router (exact fp32). One block per token, 256 threads.
// ---------------------------------------------------------------------------
__global__ void router_kernel(const float* __restrict__ x,
                              const float* __restrict__ gw,
                              const float* __restrict__ bias)
{
    const int t   = blockIdx.x;
    const int tid = threadIdx.x;
    const int lane = tid & 31;
    const int wid  = tid >> 5;

    float acc[NEXP];
    #pragma unroll
    for (int e = 0; e < NEXP; e++) acc[e] = 0.f;

    const float* xr = x + (size_t)t * HID;
    for (int h = tid; h < HID; h += 256) {
        float xv = xr[h];
        #pragma unroll
        for (int e = 0; e < NEXP; e++)
            acc[e] = fmaf(xv, gw[(size_t)e * HID + h], acc[e]);
    }

    __shared__ float sred[8][NEXP];
    __shared__ float slog[NEXP];
    #pragma unroll
    for (int e = 0; e < NEXP; e++) {
        float v = acc[e];
        #pragma unroll
        for (int o = 16; o > 0; o >>= 1) v += __shfl_down_sync(0xffffffffu, v, o);
        if (lane == 0) sred[wid][e] = v;
    }
    __syncthreads();
    if (tid < NEXP) {
        float s = 0.f;
        #pragma unroll
        for (int w = 0; w < 8; w++) s += sred[w][tid];
        slog[tid] = s;
    }
    __syncthreads();

    if (tid == 0) {
        float sc[NEXP], sb[NEXP];
        #pragma unroll
        for (int e = 0; e < NEXP; e++) {
            sc[e] = 1.f / (1.f + expf(-slog[e]));
            sb[e] = sc[e] + bias[e];
        }
        float gsc[NGROUP];
        #pragma unroll
        for (int g = 0; g < NGROUP; g++) {
            float m1 = -1e30f, m2 = -1e30f;
            #pragma unroll
            for (int j = 0; j < 4; j++) {
                float v = sb[g * 4 + j];
                if (v > m1) { m2 = m1; m1 = v; } else if (v > m2) m2 = v;
            }
            gsc[g] = m1 + m2;
        }
        int bg1 = 0;
        for (int g = 1; g < NGROUP; g++) if (gsc[g] > gsc[bg1]) bg1 = g;
        int bg2 = -1;
        for (int g = 0; g < NGROUP; g++)
            if (g != bg1 && (bg2 < 0 || gsc[g] > gsc[bg2])) bg2 = g;

        bool allowed[NEXP], used[NEXP];
        #pragma unroll
        for (int e = 0; e < NEXP; e++) {
            int g = e >> 2;
            allowed[e] = (g == bg1) || (g == bg2);
            used[e] = false;
        }
        int ids[TOPK];
        #pragma unroll
        for (int k = 0; k < TOPK; k++) {
            float best = -1e30f; int bi = -1;
            for (int e = 0; e < NEXP; e++)
                if (allowed[e] && !used[e] && sb[e] > best) { best = sb[e]; bi = e; }
            ids[k] = bi; used[bi] = true;
        }
        float ws = 0.f;
        #pragma unroll
        for (int k = 0; k < TOPK; k++) ws += sc[ids[k]];
        float inv = 1.f / ws;
        #pragma unroll
        for (int k = 0; k < TOPK; k++) {
            g_topk_ids[t * TOPK + k] = ids[k];
            g_topk_w  [t * TOPK + k] = sc[ids[k]] * inv;
        }
    }
}

// ---------------------------------------------------------------------------
// K2: deterministic per-expert compaction
// ---------------------------------------------------------------------------
__global__ void compact_kernel()
{
    const int e = blockIdx.x;
    const int t = threadIdx.x;

    int kf = -1;
    #pragma unroll
    for (int k = 0; k < TOPK; k++)
        if (g_topk_ids[t * TOPK + k] == e) kf = k;
    int flag = (kf >= 0) ? 1 : 0;

    __shared__ int s[T_TOK];
    s[t] = flag;
    __syncthreads();
    for (int off = 1; off < T_TOK; off <<= 1) {
        int v = (t >= off) ? s[t - off] : 0;
        __syncthreads();
        s[t] += v;
        __syncthreads();
    }
    int pos = s[t] - flag;
    if (flag) {
        g_tok[e * T_TOK + pos] = t;
        g_wt [e * T_TOK + pos] = g_topk_w[t * TOPK + kf] * ROUTED_SCALING;
        g_slot[t * TOPK + kf]  = e * T_TOK + pos;
    }
    if (t == T_TOK - 1) g_counts[e] = s[T_TOK - 1];
}

// ---------------------------------------------------------------------------
// TF32 mma.sync GEMM, 4-stage cp.async, 4 warps x (64x64) warp tiles.
// C[r][col0..] = A[row(r)] * B. grid: (N/BN, capacity/BM, experts), 128 thr.
// ---------------------------------------------------------------------------
template<bool GATHER>
__global__ __launch_bounds__(128, 2)
void gemm_tf32_kernel(const float* __restrict__ Abase, size_t aexp, int lda,
                      const float* __restrict__ Bbase, size_t bexp, int N, int K,
                      float* __restrict__ Cbase, size_t cexp, int ldc,
                      int nrows)
{
    const int e = blockIdx.z;
    const int n = (nrows >= 0) ? nrows : g_counts[e];
    const int row0 = blockIdx.y * BM;
    if (row0 >= n) return;
    const int col0 = blockIdx.x * BN;
    const int tid  = threadIdx.x;
    const int lane = tid & 31;
    const int wid  = tid >> 5;

    extern __shared__ float dsm[];
    __shared__ int stok[BM];

    const float* A = Abase + aexp * e;
    const float* B = Bbase + bexp * e;
    float*       C = Cbase + cexp * e;

    {
        int r = row0 + tid;
        stok[tid] = GATHER ? ((r < n) ? g_tok[e * T_TOK + r] : 0) : r;
    }
    __syncthreads();

    // ---- staging maps: each of 128 threads copies 4 A-chunks + 4 B-chunks ----
    // A: row = tid, k-chunks {0,4,8,12} within tile.
    const uint32_t szA = ((row0 + tid) < n) ? 16u : 0u;
    const float* aptr = A + (size_t)stok[tid] * lda;
    // B: k-rows {krB, krB+4, krB+8, krB+12}, n-chunk ncB.
    const int krB = tid >> 5;            // 0..3
    const int ncB = (tid & 31) * 4;      // 0..124

    const uint32_t dsm_u = smem_u32(dsm);

    const int KT = K / BK;

    // ---- warp tile: 64x64. mb 0..3 (m16), nb 0..7 (n8) ----
    const int warp_m = (wid >> 1) * 64;
    const int warp_n = (wid & 1) * 64;

    float acc[4][8][4];
    #pragma unroll
    for (int mb = 0; mb < 4; mb++)
        #pragma unroll
        for (int nb = 0; nb < 8; nb++)
            #pragma unroll
            for (int r = 0; r < 4; r++) acc[mb][nb][r] = 0.f;

    // ---- prologue: stages 0..NSTAGE-2 ----
    #pragma unroll
    for (int s = 0; s < NSTAGE - 1; s++) {
        if (s < KT) {
            const int k0 = s * BK;
            const uint32_t soA = (uint32_t)(s * AS_FLOATS);
            const uint32_t soB = (uint32_t)(A_TOTAL + s * BS_FLOATS);
            #pragma unroll
            for (int j = 0; j < 4; j++)
                cp_async16(dsm_u + (soA + (uint32_t)tid * PADA + j * 4) * 4u,
                           aptr + k0 + j * 4, szA);
            #pragma unroll
            for (int j = 0; j < 4; j++)
                cp_async16(dsm_u + (soB + (uint32_t)(krB + 4 * j) * PADB + ncB) * 4u,
                           B + (size_t)(k0 + krB + 4 * j) * N + col0 + ncB, 16u);
        }
        CP_COMMIT();
    }

    for (int t = 0; t < KT; t++) {
        CP_WAIT(NSTAGE - 2);
        __syncthreads();

        // issue copies for tile t+NSTAGE-1 (its buffer was consumed at t-1)
        {
            const int tn = t + NSTAGE - 1;
            if (tn < KT) {
                const int s = tn & (NSTAGE - 1);
                const int k0 = tn * BK;
                const uint32_t soA = (uint32_t)(s * AS_FLOATS);
                const uint32_t soB = (uint32_t)(A_TOTAL + s * BS_FLOATS);
                #pragma unroll
                for (int j = 0; j < 4; j++)
                    cp_async16(dsm_u + (soA + (uint32_t)tid * PADA + j * 4) * 4u,
                               aptr + k0 + j * 4, szA);
                #pragma unroll
                for (int j = 0; j < 4; j++)
                    cp_async16(dsm_u + (soB + (uint32_t)(krB + 4 * j) * PADB + ncB) * 4u,
                               B + (size_t)(k0 + krB + 4 * j) * N + col0 + ncB, 16u);
            }
            CP_COMMIT();
        }

        // ---- consume tile t ----
        const int s = t & (NSTAGE - 1);
        const float* As = dsm + s * AS_FLOATS;
        const float* Bs = dsm + A_TOTAL + s * BS_FLOATS;

        #pragma unroll
        for (int ks = 0; ks < 2; ks++) {
            uint32_t af[4][4];
            #pragma unroll
            for (int mb = 0; mb < 4; mb++) {
                const int r0 = warp_m + mb * 16 + (lane >> 2);
                const int c0 = ks * 8 + (lane & 3);
                af[mb][0] = f2tf32(As[ r0      * PADA + c0]);
                af[mb][1] = f2tf32(As[(r0 + 8) * PADA + c0]);
                af[mb][2] = f2tf32(As[ r0      * PADA + c0 + 4]);
                af[mb][3] = f2tf32(As[(r0 + 8) * PADA + c0 + 4]);
            }
            uint32_t bf[8][2];
            #pragma unroll
            for (int nb = 0; nb < 8; nb++) {
                const int kr = ks * 8 + (lane & 3);
                const int cc = warp_n + nb * 8 + (lane >> 2);
                bf[nb][0] = f2tf32(Bs[ kr      * PADB + cc]);
                bf[nb][1] = f2tf32(Bs[(kr + 4) * PADB + cc]);
            }
            #pragma unroll
            for (int mb = 0; mb < 4; mb++)
                #pragma unroll
                for (int nb = 0; nb < 8; nb++)
                    mma_tf32(acc[mb][nb], af[mb], bf[nb]);
        }
    }

    // ---- epilogue ----
    #pragma unroll
    for (int mb = 0; mb < 4; mb++) {
        const int rA = row0 + warp_m + mb * 16 + (lane >> 2);
        const int rB = rA + 8;
        #pragma unroll
        for (int nb = 0; nb < 8; nb++) {
            const int c = col0 + warp_n + nb * 8 + (lane & 3) * 2;
            if (rA < n)
                *(float2*)&C[(size_t)rA * ldc + c] = make_float2(acc[mb][nb][0], acc[mb][nb][1]);
            if (rB < n)
                *(float2*)&C[(size_t)rB * ldc + c] = make_float2(acc[mb][nb][2], acc[mb][nb][3]);
        }
    }
}

// ---------------------------------------------------------------------------
// Elementwise activations (in-place, fp32)
// ---------------------------------------------------------------------------
__device__ __forceinline__ float silu_mul(float g, float u) {
    return (g / (1.f + __expf(-g))) * u;
}

__global__ void act_routed_kernel()
{
    const int slot = blockIdx.x;
    const int e = slot >> 10, pos = slot & (T_TOK - 1);
    if (pos >= g_counts[e]) return;
    const float w = g_wt[slot];
    float4* row = (float4*)(g_gu + (size_t)slot * (2 * IMID));
    const int nq = IMID / 4;
    for (int i = threadIdx.x; i < nq; i += blockDim.x) {
        float4 g = row[i], u = row[i + nq];
        float4 v;
        v.x = silu_mul(g.x, u.x) * w;
        v.y = silu_mul(g.y, u.y) * w;
        v.z = silu_mul(g.z, u.z) * w;
        v.w = silu_mul(g.w, u.w) * w;
        row[i] = v;
    }
}

__global__ void act_shared_kernel()
{
    const int t = blockIdx.x;
    float4* row = (float4*)(g_sgu + (size_t)t * (2 * ISH));
    const int nq = ISH / 4;
    for (int i = threadIdx.x; i < nq; i += blockDim.x) {
        float4 g = row[i], u = row[i + nq];
        float4 v;
        v.x = silu_mul(g.x, u.x);
        v.y = silu_mul(g.y, u.y);
        v.z = silu_mul(g.z, u.z);
        v.w = silu_mul(g.w, u.w);
        row[i] = v;
    }
}

// ---------------------------------------------------------------------------
// Final combine: out[t] += sum_k g_down[slot[t][k]]
// ---------------------------------------------------------------------------
__global__ void combine_kernel(float* __restrict__ out)
{
    const int idx = blockIdx.x * blockDim.x + threadIdx.x;
    const int t  = idx >> 9;
    const int hc = (idx & 511) * 4;

    float4 acc = *reinterpret_cast<const float4*>(out + (size_t)t * HID + hc);
    #pragma unroll
    for (int k = 0; k < TOPK; k++) {
        int s = g_slot[t * TOPK + k];
        float4 v = *reinterpret_cast<const float4*>(g_down + (size_t)s * HID + hc);
        acc.x += v.x; acc.y += v.y; acc.z += v.z; acc.w += v.w;
    }
    *reinterpret_cast<float4*>(out + (size_t)t * HID + hc) = acc;
}

// ---------------------------------------------------------------------------
extern "C" void kernel_launch(void* const* d_in, const int* in_sizes, int n_in,
                              void* d_out, int out_size)
{
    const float* x    = (const float*)d_in[0];  // [1024, 2048]
    const float* gw   = (const float*)d_in[1];  // [16, 2048]
    const float* bias = (const float*)d_in[2];  // [16]
    const float* wgu  = (const float*)d_in[3];  // [16, 2048, 2816]
    const float* wd   = (const float*)d_in[4];  // [16, 1408, 2048]
    const float* sgu  = (const float*)d_in[5];  // [2048, 5632]
    const float* sd   = (const float*)d_in[6];  // [2816, 2048]
    float* out = (float*)d_out;                 // [1024, 2048]

    (void)in_sizes; (void)n_in; (void)out_size;

    cudaFuncSetAttribute(gemm_tf32_kernel<true>,
                         cudaFuncAttributeMaxDynamicSharedMemorySize, DSM_BYTES);
    cudaFuncSetAttribute(gemm_tf32_kernel<false>,
                         cudaFuncAttributeMaxDynamicSharedMemorySize, DSM_BYTES);

    router_kernel<<<T_TOK, 256>>>(x, gw, bias);
    compact_kernel<<<NEXP, T_TOK>>>();

    float* gu_ptr = nullptr;  float* down_ptr = nullptr;  float* sgu_ptr = nullptr;
    cudaGetSymbolAddress((void**)&gu_ptr,   g_gu);
    cudaGetSymbolAddress((void**)&down_ptr, g_down);
    cudaGetSymbolAddress((void**)&sgu_ptr,  g_sgu);

    // routed gate_up: g_gu[slot][0..2816) = x[tok] * wgu[e]
    {
        dim3 grid((2 * IMID) / BN, T_TOK / BM, NEXP);   // (22, 8, 16)
        gemm_tf32_kernel<true><<<grid, 128, DSM_BYTES>>>(
            x, 0, HID,
            wgu, (size_t)HID * (2 * IMID), 2 * IMID, HID,
            gu_ptr, (size_t)T_TOK * (2 * IMID), 2 * IMID,
            -1);
    }
    // shared gate_up: g_sgu = x * sgu
    {
        dim3 grid((2 * ISH) / BN, T_TOK / BM, 1);       // (44, 8)
        gemm_tf32_kernel<false><<<grid, 128, DSM_BYTES>>>(
            x, 0, HID,
            sgu, 0, 2 * ISH, HID,
            sgu_ptr, 0, 2 * ISH,
            T_TOK);
    }

    act_routed_kernel<<<NEXP * T_TOK, 256>>>();
    act_shared_kernel<<<T_TOK, 256>>>();

    // routed down: g_down[slot] = act[slot] * wd[e]
    {
        dim3 grid(HID / BN, T_TOK / BM, NEXP);          // (16, 8, 16)
        gemm_tf32_kernel<false><<<grid, 128, DSM_BYTES>>>(
            gu_ptr, (size_t)T_TOK * (2 * IMID), 2 * IMID,
            wd, (size_t)IMID * HID, HID, IMID,
            down_ptr, (size_t)T_TOK * HID, HID,
            -1);
    }
    // shared down: out = sact * sd
    {
        dim3 grid(HID / BN, T_TOK / BM, 1);             // (16, 8)
        gemm_tf32_kernel<false><<<grid, 128, DSM_BYTES>>>(
            sgu_ptr, 0, 2 * ISH,
            sd, 0, HID, ISH,
            out, 0, HID,
            T_TOK);
    }

    combine_kernel<<<(T_TOK * (HID / 4)) / 256, 256>>>(out);
}

// round 17
// speedup vs baseline: 1.1785x; 1.1785x over previous
#include <cuda_runtime.h>
#include <math.h>
#include <stdint.h>

// ---------------------------------------------------------------------------
// DeepseekV2MoE: T=1024, H=2048, I=1408, E=16, top4 of 16 (grouped), IS=2816.
// R16: R12 GEMM shape (8 warps x 64x32, 256 thr, 4-stage cp.async for A) with
// ALL cvt removed from the consumer loop:
//   - A operands pre-rounded to tf32 in GMEM (x via tiny kernel; g_gu/g_sgu
//     rounded inside the act kernels for free)
//   - B (weights) converted at staging: LDG(t+1) at loop top, CVT+STS after
//     compute, 2-stage smem double buffer
// Consumer inner loop: raw LDS + HMMA only. Router exact fp32.
// ---------------------------------------------------------------------------

#define T_TOK 1024
#define HID   2048
#define IMID  1408
#define NEXP  16
#define ISH   2816
#define NGROUP 4
#define TOPK   4
#define ROUTED_SCALING 2.5f

#define BM 128
#define BN 128
#define BK 16
#define NSTAGE 4
#define PADA 20            // As row pitch (floats)
#define PADB 136           // Bs row pitch (floats)
#define AS_FLOATS (BM * PADA)            // 2560
#define BS_FLOATS (BK * PADB)            // 2176
#define A_TOTAL   (NSTAGE * AS_FLOATS)   // 10240
#define DSM_FLOATS (A_TOTAL + 2 * BS_FLOATS)   // 14592 floats
#define DSM_BYTES (DSM_FLOATS * 4)             // 58368 B

// ---------------- scratch (device globals; allocation-free) ----------------
__device__ float g_xtf [(size_t)T_TOK * HID];                // tf32-rounded x
__device__ float g_gu  [(size_t)NEXP * T_TOK * (2 * IMID)];
__device__ float g_down[(size_t)NEXP * T_TOK * HID];
__device__ float g_sgu [(size_t)T_TOK * (2 * ISH)];
__device__ int   g_topk_ids[T_TOK * TOPK];
__device__ float g_topk_w  [T_TOK * TOPK];
__device__ int   g_tok [NEXP * T_TOK];
__device__ float g_wt  [NEXP * T_TOK];
__device__ int   g_counts[NEXP];
__device__ int   g_slot[T_TOK * TOPK];

// ---------------------------------------------------------------------------
// helpers
// ---------------------------------------------------------------------------
__device__ __forceinline__ uint32_t smem_u32(const void* p) {
    uint32_t a;
    asm("{ .reg .u64 t; cvta.to.shared.u64 t, %1; cvt.u32.u64 %0, t; }"
        : "=r"(a) : "l"(p));
    return a;
}

__device__ __forceinline__ uint32_t f2tf32(float x) {
    uint32_t r;
    asm("cvt.rna.tf32.f32 %0, %1;" : "=r"(r) : "f"(x));
    return r;
}
__device__ __forceinline__ float f2tf32f(float x) {
    return __uint_as_float(f2tf32(x));
}

__device__ __forceinline__ void cp_async16(uint32_t dst, const void* src, uint32_t src_sz) {
    asm volatile("cp.async.cg.shared.global [%0], [%1], 16, %2;"
                 :: "r"(dst), "l"(src), "r"(src_sz) : "memory");
}

#define CP_COMMIT() asm volatile("cp.async.commit_group;" ::: "memory")
#define CP_WAIT(n)  asm volatile("cp.async.wait_group %0;" :: "n"(n) : "memory")

__device__ __forceinline__ void mma_tf32(float c[4], const uint32_t a[4], const uint32_t b[2]) {
    asm volatile(
        "mma.sync.aligned.m16n8k8.row.col.f32.tf32.tf32.f32 "
        "{%0,%1,%2,%3}, {%4,%5,%6,%7}, {%8,%9}, {%0,%1,%2,%3};\n"
        : "+f"(c[0]), "+f"(c[1]), "+f"(c[2]), "+f"(c[3])
        : "r"(a[0]), "r"(a[1]), "r"(a[2]), "r"(a[3]), "r"(b[0]), "r"(b[1]));
}

// ---------------------------------------------------------------------------
// K0: round x to tf32 (A-side pre-rounding for the gate_up GEMMs)
// ---------------------------------------------------------------------------
__global__ void round_x_kernel(const float* __restrict__ x)
{
    const int i = blockIdx.x * blockDim.x + threadIdx.x;   // over T*H/4
    float4 v = *reinterpret_cast<const float4*>(x + (size_t)i * 4);
    v.x = f2tf32f(v.x); v.y = f2tf32f(v.y);
    v.z = f2tf32f(v.z); v.w = f2tf32f(v.w);
    *reinterpret_cast<float4*>(g_xtf + (size_t)i * 4) = v;
}

// ---------------------------------------------------------------------------
// K1: router (exact fp32). One block per token, 256 threads.
// ---------------------------------------------------------------------------
__global__ void router_kernel(const float* __restrict__ x,
                              const float* __restrict__ gw,
                              const float* __restrict__ bias)
{
    const int t   = blockIdx.x;
    const int tid = threadIdx.x;
    const int lane = tid & 31;
    const int wid  = tid >> 5;

    float acc[NEXP];
    #pragma unroll
    for (int e = 0; e < NEXP; e++) acc[e] = 0.f;

    const float* xr = x + (size_t)t * HID;
    for (int h = tid; h < HID; h += 256) {
        float xv = xr[h];
        #pragma unroll
        for (int e = 0; e < NEXP; e++)
            acc[e] = fmaf(xv, gw[(size_t)e * HID + h], acc[e]);
    }

    __shared__ float sred[8][NEXP];
    __shared__ float slog[NEXP];
    #pragma unroll
    for (int e = 0; e < NEXP; e++) {
        float v = acc[e];
        #pragma unroll
        for (int o = 16; o > 0; o >>= 1) v += __shfl_down_sync(0xffffffffu, v, o);
        if (lane == 0) sred[wid][e] = v;
    }
    __syncthreads();
    if (tid < NEXP) {
        float s = 0.f;
        #pragma unroll
        for (int w = 0; w < 8; w++) s += sred[w][tid];
        slog[tid] = s;
    }
    __syncthreads();

    if (tid == 0) {
        float sc[NEXP], sb[NEXP];
        #pragma unroll
        for (int e = 0; e < NEXP; e++) {
            sc[e] = 1.f / (1.f + expf(-slog[e]));
            sb[e] = sc[e] + bias[e];
        }
        float gsc[NGROUP];
        #pragma unroll
        for (int g = 0; g < NGROUP; g++) {
            float m1 = -1e30f, m2 = -1e30f;
            #pragma unroll
            for (int j = 0; j < 4; j++) {
                float v = sb[g * 4 + j];
                if (v > m1) { m2 = m1; m1 = v; } else if (v > m2) m2 = v;
            }
            gsc[g] = m1 + m2;
        }
        int bg1 = 0;
        for (int g = 1; g < NGROUP; g++) if (gsc[g] > gsc[bg1]) bg1 = g;
        int bg2 = -1;
        for (int g = 0; g < NGROUP; g++)
            if (g != bg1 && (bg2 < 0 || gsc[g] > gsc[bg2])) bg2 = g;

        bool allowed[NEXP], used[NEXP];
        #pragma unroll
        for (int e = 0; e < NEXP; e++) {
            int g = e >> 2;
            allowed[e] = (g == bg1) || (g == bg2);
            used[e] = false;
        }
        int ids[TOPK];
        #pragma unroll
        for (int k = 0; k < TOPK; k++) {
            float best = -1e30f; int bi = -1;
            for (int e = 0; e < NEXP; e++)
                if (allowed[e] && !used[e] && sb[e] > best) { best = sb[e]; bi = e; }
            ids[k] = bi; used[bi] = true;
        }
        float ws = 0.f;
        #pragma unroll
        for (int k = 0; k < TOPK; k++) ws += sc[ids[k]];
        float inv = 1.f / ws;
        #pragma unroll
        for (int k = 0; k < TOPK; k++) {
            g_topk_ids[t * TOPK + k] = ids[k];
            g_topk_w  [t * TOPK + k] = sc[ids[k]] * inv;
        }
    }
}

// ---------------------------------------------------------------------------
// K2: deterministic per-expert compaction
// ---------------------------------------------------------------------------
__global__ void compact_kernel()
{
    const int e = blockIdx.x;
    const int t = threadIdx.x;

    int kf = -1;
    #pragma unroll
    for (int k = 0; k < TOPK; k++)
        if (g_topk_ids[t * TOPK + k] == e) kf = k;
    int flag = (kf >= 0) ? 1 : 0;

    __shared__ int s[T_TOK];
    s[t] = flag;
    __syncthreads();
    for (int off = 1; off < T_TOK; off <<= 1) {
        int v = (t >= off) ? s[t - off] : 0;
        __syncthreads();
        s[t] += v;
        __syncthreads();
    }
    int pos = s[t] - flag;
    if (flag) {
        g_tok[e * T_TOK + pos] = t;
        g_wt [e * T_TOK + pos] = g_topk_w[t * TOPK + kf] * ROUTED_SCALING;
        g_slot[t * TOPK + kf]  = e * T_TOK + pos;
    }
    if (t == T_TOK - 1) g_counts[e] = s[T_TOK - 1];
}

// ---------------------------------------------------------------------------
// TF32 mma.sync GEMM. A: 4-stage cp.async (pre-rounded tf32 source).
// B: LDG early / CVT+STS late, 2-stage smem double buffer.
// Consumer loop: raw LDS + HMMA only (zero CVT).
// grid: (N/BN, capacity/BM, experts), 256 threads.
// ---------------------------------------------------------------------------
template<bool GATHER>
__global__ __launch_bounds__(256, 2)
void gemm_tf32_kernel(const float* __restrict__ Abase, size_t aexp, int lda,
                      const float* __restrict__ Bbase, size_t bexp, int N, int K,
                      float* __restrict__ Cbase, size_t cexp, int ldc,
                      int nrows)
{
    const int e = blockIdx.z;
    const int n = (nrows >= 0) ? nrows : g_counts[e];
    const int row0 = blockIdx.y * BM;
    if (row0 >= n) return;
    const int col0 = blockIdx.x * BN;
    const int tid  = threadIdx.x;
    const int lane = tid & 31;
    const int wid  = tid >> 5;

    extern __shared__ float dsm[];
    __shared__ int stok[BM];

    const float* A = Abase + aexp * e;
    const float* B = Bbase + bexp * e;
    float*       C = Cbase + cexp * e;

    if (tid < BM) {
        int r = row0 + tid;
        stok[tid] = GATHER ? ((r < n) ? g_tok[e * T_TOK + r] : 0) : r;
    }
    __syncthreads();

    // ---- A staging map (cp.async, 512 chunks of 16B) ----
    const int rA0 = tid >> 2;            // 0..63
    const int rA1 = rA0 + 64;            // 64..127
    const int kcA = (tid & 3) * 4;       // 0,4,8,12
    const uint32_t szA0 = ((row0 + rA0) < n) ? 16u : 0u;
    const uint32_t szA1 = ((row0 + rA1) < n) ? 16u : 0u;
    const float* aptr0 = A + (size_t)stok[rA0] * lda + kcA;
    const float* aptr1 = A + (size_t)stok[rA1] * lda + kcA;

    // ---- B staging map (LDG + CVT + STS, 2-stage) ----
    const int krB = tid >> 5;            // 0..7
    const int ncB = (tid & 31) * 4;      // 0..124
    const float* bptr0 = B + (size_t)krB * N + col0 + ncB;
    const float* bptr1 = B + (size_t)(krB + 8) * N + col0 + ncB;
    float* bs0 = dsm + A_TOTAL + krB * PADB + ncB;
    float* bs1 = dsm + A_TOTAL + (krB + 8) * PADB + ncB;

    const uint32_t dsm_u = smem_u32(dsm);
    const uint32_t dA0 = dsm_u + (uint32_t)(rA0 * PADA + kcA) * 4u;
    const uint32_t dA1 = dsm_u + (uint32_t)(rA1 * PADA + kcA) * 4u;

    const int KT = K / BK;

    const int warp_m = (wid >> 2) * 64;
    const int warp_n = (wid & 3) * 32;

    float acc[4][4][4];
    #pragma unroll
    for (int mb = 0; mb < 4; mb++)
        #pragma unroll
        for (int nb = 0; nb < 4; nb++)
            #pragma unroll
            for (int r = 0; r < 4; r++) acc[mb][nb][r] = 0.f;

    // ---- prologue ----
    // B(0): load + convert + store into stage 0 (before any barrier)
    {
        float4 b0 = __ldg((const float4*)bptr0);
        float4 b1 = __ldg((const float4*)bptr1);
        *(uint4*)bs0 = make_uint4(f2tf32(b0.x), f2tf32(b0.y), f2tf32(b0.z), f2tf32(b0.w));
        *(uint4*)bs1 = make_uint4(f2tf32(b1.x), f2tf32(b1.y), f2tf32(b1.z), f2tf32(b1.w));
    }
    // A stages 0..NSTAGE-2
    #pragma unroll
    for (int s = 0; s < NSTAGE - 1; s++) {
        if (s < KT) {
            const int k0 = s * BK;
            const uint32_t soA = (uint32_t)(s * AS_FLOATS) * 4u;
            cp_async16(dA0 + soA, aptr0 + k0, szA0);
            cp_async16(dA1 + soA, aptr1 + k0, szA1);
        }
        CP_COMMIT();
    }

    for (int t = 0; t < KT; t++) {
        // B(t+1): issue LDG as early as possible (global read; no smem hazard)
        float4 nb0, nb1;
        const bool have_next = (t + 1 < KT);
        if (have_next) {
            const size_t koff = (size_t)(t + 1) * BK * N;
            nb0 = __ldg((const float4*)(bptr0 + koff));
            nb1 = __ldg((const float4*)(bptr1 + koff));
        }

        CP_WAIT(NSTAGE - 2);
        __syncthreads();   // A(t) visible; all warps done with compute(t-1);
                           // B(t) STS (end of t-1) ordered for all consumers

        // A(t+NSTAGE-1) cp.async
        {
            const int tn = t + NSTAGE - 1;
            if (tn < KT) {
                const int s = tn & (NSTAGE - 1);
                const int k0 = tn * BK;
                const uint32_t soA = (uint32_t)(s * AS_FLOATS) * 4u;
                cp_async16(dA0 + soA, aptr0 + k0, szA0);
                cp_async16(dA1 + soA, aptr1 + k0, szA1);
            }
            CP_COMMIT();
        }

        // ---- consume tile t: raw LDS + HMMA only ----
        const float* As = dsm + (t & (NSTAGE - 1)) * AS_FLOATS;
        const float* Bs = dsm + A_TOTAL + (t & 1) * BS_FLOATS;

        #pragma unroll
        for (int ks = 0; ks < 2; ks++) {
            uint32_t af[4][4];
            #pragma unroll
            for (int mb = 0; mb < 4; mb++) {
                const int r0 = warp_m + mb * 16 + (lane >> 2);
                const int c0 = ks * 8 + (lane & 3);
                af[mb][0] = __float_as_uint(As[ r0      * PADA + c0]);
                af[mb][1] = __float_as_uint(As[(r0 + 8) * PADA + c0]);
                af[mb][2] = __float_as_uint(As[ r0      * PADA + c0 + 4]);
                af[mb][3] = __float_as_uint(As[(r0 + 8) * PADA + c0 + 4]);
            }
            uint32_t bf[4][2];
            #pragma unroll
            for (int nb = 0; nb < 4; nb++) {
                const int kr = ks * 8 + (lane & 3);
                const int cc = warp_n + nb * 8 + (lane >> 2);
                bf[nb][0] = __float_as_uint(Bs[ kr      * PADB + cc]);
                bf[nb][1] = __float_as_uint(Bs[(kr + 4) * PADB + cc]);
            }
            #pragma unroll
            for (int mb = 0; mb < 4; mb++)
                #pragma unroll
                for (int nb = 0; nb < 4; nb++)
                    mma_tf32(acc[mb][nb], af[mb], bf[nb]);
        }

        // ---- B(t+1): convert + store into stage (t+1)&1 ----
        // Safe: consumers of stage (t+1)&1 [= tile t+1] wait on the barrier at
        // the top of iteration t+1; stage (t+1)&1 != t&1 being read this iter;
        // previous owner tile (t-1) finished before the barrier at top of t.
        if (have_next) {
            const uint32_t so = (uint32_t)(((t + 1) & 1) * BS_FLOATS);
            *(uint4*)(bs0 + so) = make_uint4(f2tf32(nb0.x), f2tf32(nb0.y), f2tf32(nb0.z), f2tf32(nb0.w));
            *(uint4*)(bs1 + so) = make_uint4(f2tf32(nb1.x), f2tf32(nb1.y), f2tf32(nb1.z), f2tf32(nb1.w));
        }
    }

    // ---- epilogue ----
    #pragma unroll
    for (int mb = 0; mb < 4; mb++) {
        const int rA = row0 + warp_m + mb * 16 + (lane >> 2);
        const int rB = rA + 8;
        #pragma unroll
        for (int nb = 0; nb < 4; nb++) {
            const int c = col0 + warp_n + nb * 8 + (lane & 3) * 2;
            if (rA < n)
                *(float2*)&C[(size_t)rA * ldc + c] = make_float2(acc[mb][nb][0], acc[mb][nb][1]);
            if (rB < n)
                *(float2*)&C[(size_t)rB * ldc + c] = make_float2(acc[mb][nb][2], acc[mb][nb][3]);
        }
    }
}

// ---------------------------------------------------------------------------
// Elementwise activations (in-place, outputs tf32-rounded for next GEMM's A)
// ---------------------------------------------------------------------------
__device__ __forceinline__ float silu_mul(float g, float u) {
    return (g / (1.f + __expf(-g))) * u;
}

__global__ void act_routed_kernel()
{
    const int slot = blockIdx.x;
    const int e = slot >> 10, pos = slot & (T_TOK - 1);
    if (pos >= g_counts[e]) return;
    const float w = g_wt[slot];
    float4* row = (float4*)(g_gu + (size_t)slot * (2 * IMID));
    const int nq = IMID / 4;
    for (int i = threadIdx.x; i < nq; i += blockDim.x) {
        float4 g = row[i], u = row[i + nq];
        float4 v;
        v.x = f2tf32f(silu_mul(g.x, u.x) * w);
        v.y = f2tf32f(silu_mul(g.y, u.y) * w);
        v.z = f2tf32f(silu_mul(g.z, u.z) * w);
        v.w = f2tf32f(silu_mul(g.w, u.w) * w);
        row[i] = v;
    }
}

__global__ void act_shared_kernel()
{
    const int t = blockIdx.x;
    float4* row = (float4*)(g_sgu + (size_t)t * (2 * ISH));
    const int nq = ISH / 4;
    for (int i = threadIdx.x; i < nq; i += blockDim.x) {
        float4 g = row[i], u = row[i + nq];
        float4 v;
        v.x = f2tf32f(silu_mul(g.x, u.x));
        v.y = f2tf32f(silu_mul(g.y, u.y));
        v.z = f2tf32f(silu_mul(g.z, u.z));
        v.w = f2tf32f(silu_mul(g.w, u.w));
        row[i] = v;
    }
}

// ---------------------------------------------------------------------------
// Final combine: out[t] += sum_k g_down[slot[t][k]]
// ---------------------------------------------------------------------------
__global__ void combine_kernel(float* __restrict__ out)
{
    const int idx = blockIdx.x * blockDim.x + threadIdx.x;
    const int t  = idx >> 9;
    const int hc = (idx & 511) * 4;

    float4 acc = *reinterpret_cast<const float4*>(out + (size_t)t * HID + hc);
    #pragma unroll
    for (int k = 0; k < TOPK; k++) {
        int s = g_slot[t * TOPK + k];
        float4 v = *reinterpret_cast<const float4*>(g_down + (size_t)s * HID + hc);
        acc.x += v.x; acc.y += v.y; acc.z += v.z; acc.w += v.w;
    }
    *reinterpret_cast<float4*>(out + (size_t)t * HID + hc) = acc;
}

// ---------------------------------------------------------------------------
extern "C" void kernel_launch(void* const* d_in, const int* in_sizes, int n_in,
                              void* d_out, int out_size)
{
    const float* x    = (const float*)d_in[0];  // [1024, 2048]
    const float* gw   = (const float*)d_in[1];  // [16, 2048]
    const float* bias = (const float*)d_in[2];  // [16]
    const float* wgu  = (const float*)d_in[3];  // [16, 2048, 2816]
    const float* wd   = (const float*)d_in[4];  // [16, 1408, 2048]
    const float* sgu  = (const float*)d_in[5];  // [2048, 5632]
    const float* sd   = (const float*)d_in[6];  // [2816, 2048]
    float* out = (float*)d_out;                 // [1024, 2048]

    (void)in_sizes; (void)n_in; (void)out_size;

    cudaFuncSetAttribute(gemm_tf32_kernel<true>,
                         cudaFuncAttributeMaxDynamicSharedMemorySize, DSM_BYTES);
    cudaFuncSetAttribute(gemm_tf32_kernel<false>,
                         cudaFuncAttributeMaxDynamicSharedMemorySize, DSM_BYTES);

    round_x_kernel<<<(T_TOK * HID / 4) / 256, 256>>>(x);
    router_kernel<<<T_TOK, 256>>>(x, gw, bias);
    compact_kernel<<<NEXP, T_TOK>>>();

    float* xtf_ptr = nullptr; float* gu_ptr = nullptr;
    float* down_ptr = nullptr; float* sgu_ptr = nullptr;
    cudaGetSymbolAddress((void**)&xtf_ptr,  g_xtf);
    cudaGetSymbolAddress((void**)&gu_ptr,   g_gu);
    cudaGetSymbolAddress((void**)&down_ptr, g_down);
    cudaGetSymbolAddress((void**)&sgu_ptr,  g_sgu);

    // routed gate_up: g_gu[slot][0..2816) = xtf[tok] * wgu[e]
    {
        dim3 grid((2 * IMID) / BN, T_TOK / BM, NEXP);   // (22, 8, 16)
        gemm_tf32_kernel<true><<<grid, 256, DSM_BYTES>>>(
            xtf_ptr, 0, HID,
            wgu, (size_t)HID * (2 * IMID), 2 * IMID, HID,
            gu_ptr, (size_t)T_TOK * (2 * IMID), 2 * IMID,
            -1);
    }
    // shared gate_up: g_sgu = xtf * sgu
    {
        dim3 grid((2 * ISH) / BN, T_TOK / BM, 1);       // (44, 8)
        gemm_tf32_kernel<false><<<grid, 256, DSM_BYTES>>>(
            xtf_ptr, 0, HID,
            sgu, 0, 2 * ISH, HID,
            sgu_ptr, 0, 2 * ISH,
            T_TOK);
    }

    act_routed_kernel<<<NEXP * T_TOK, 256>>>();
    act_shared_kernel<<<T_TOK, 256>>>();

    // routed down: g_down[slot] = act[slot] * wd[e]   (act pre-rounded)
    {
        dim3 grid(HID / BN, T_TOK / BM, NEXP);          // (16, 8, 16)
        gemm_tf32_kernel<false><<<grid, 256, DSM_BYTES>>>(
            gu_ptr, (size_t)T_TOK * (2 * IMID), 2 * IMID,
            wd, (size_t)IMID * HID, HID, IMID,
            down_ptr, (size_t)T_TOK * HID, HID,
            -1);
    }
    // shared down: out = sact * sd   (sact pre-rounded)
    {
        dim3 grid(HID / BN, T_TOK / BM, 1);             // (16, 8)
        gemm_tf32_kernel<false><<<grid, 256, DSM_BYTES>>>(
            sgu_ptr, 0, 2 * ISH,
            sd, 0, HID, ISH,
            out, 0, HID,
            T_TOK);
    }

    combine_kernel<<<(T_TOK * (HID / 4)) / 256, 256>>>(out);
}